// round 7
// baseline (speedup 1.0000x reference)
#include <cuda_runtime.h>

// SigNet: depth-4 path signature (C=8 incl. time) + linear head.
// K1: 8-way segmented scalar Chen scan, software-pipelined (prefetch t+1),
//     factored updates, in-smem tree combine. No dynamic register indexing.
// K2: split-k GEMM (KSPLIT=21), padded smem tiles + float4 inner loop.
// K3: reduce + bias.

#define NB      128
#define SLEN    1024
#define NSEG    8
#define SEG     128
#define CIN     7
#define SIGCH   4680          // 8 + 64 + 512 + 4096
#define YSTRIDE 4704
#define DOUT    256
#define KSPLIT  21
#define KCHUNK  224           // 21*224 = 4704

__device__ float g_y[NB * YSTRIDE];
__device__ float g_part[KSPLIT * NB * DOUT];

// smem: vs[1024][8] = 8192 floats, then reused as T[8][4680] = 37440 floats.
#define SMEM_FLOATS (NSEG * SIGCH)     // 37440 floats = 149760 B

// ---- Chen combine pieces (X = A o B, A earlier in time) ----
__device__ __forceinline__ void chen_l4(const float* __restrict__ A,
                                        const float* __restrict__ B,
                                        float* __restrict__ X, int lane, int nth)
{
    for (int e = lane; e < 4096; e += nth) {
        float v = A[584 + e] + B[584 + e];
        v = fmaf(A[e >> 9],        B[72 + (e & 511)], v);
        v = fmaf(A[8 + (e >> 6)],  B[8  + (e & 63)],  v);
        v = fmaf(A[72 + (e >> 3)], B[e & 7],          v);
        X[584 + e] = v;
    }
}
__device__ __forceinline__ void chen_l3(const float* __restrict__ A,
                                        const float* __restrict__ B,
                                        float* __restrict__ X, int lane, int nth)
{
    for (int e = lane; e < 512; e += nth) {
        float v = A[72 + e] + B[72 + e];
        v = fmaf(A[e >> 6],       B[8 + (e & 63)], v);
        v = fmaf(A[8 + (e >> 3)], B[e & 7],        v);
        X[72 + e] = v;
    }
}

// In-place combine: A <- A o B. nth threads, lane in [0,nth).
// Internal syncs are CTA-wide; every thread runs the same sequence.
__device__ __forceinline__ void chen_inplace(float* __restrict__ A,
                                             const float* __restrict__ B,
                                             int lane, int nth)
{
    chen_l4(A, B, A, lane, nth);      // reads A[0..584), writes A[584..)
    __syncthreads();
    chen_l3(A, B, A, lane, nth);      // reads A[0..72), writes A[72..584)
    float v2 = 0.0f, v1 = 0.0f;
    if (lane < 64) v2 = A[8 + lane] + B[8 + lane] + A[lane >> 3] * B[lane & 7];
    if (lane < 8)  v1 = A[lane] + B[lane];
    __syncthreads();
    if (lane < 64) A[8 + lane] = v2;
    if (lane < 8)  A[lane] = v1;
}

// ---------------------------------------------------------------------------
// Kernel 1: segmented scan. 1 CTA/batch, 512 threads = 8 groups x 64.
// Thread u=tid&63 owns (a,b)=(u>>3,u&7): all 8 c, all 8 d (64 L4 accumulators).
// ---------------------------------------------------------------------------
__global__ __launch_bounds__(512, 1) void sig_scan_kernel(const float* __restrict__ inp)
{
    extern __shared__ float sm[];
    const int b   = blockIdx.x;
    const int tid = threadIdx.x;

    // Build increments into sm[0..8192). Basepoint 0: first inc = first sample.
    const float dt = 1.0f / 1023.0f;
    const float* x = inp + (size_t)b * SLEN * CIN;
    for (int i = tid; i < SLEN * CIN; i += 512) {
        int t = i / CIN, c = i - t * CIN;
        float cur  = x[i];
        float prev = (t == 0) ? 0.0f : x[i - CIN];
        sm[t * 8 + c + 1] = cur - prev;
    }
    for (int t = tid; t < SLEN; t += 512)
        sm[t * 8] = (t == 0) ? 0.0f : dt;
    __syncthreads();

    const int g  = tid >> 6;          // segment 0..7
    const int u  = tid & 63;          // (a,b)
    const int a  = u >> 3;
    const int bb = u & 7;

    float s1 = 0.0f, s2 = 0.0f;
    float s3[8];
    float sig4[64];
#pragma unroll
    for (int i = 0; i < 8; i++) s3[i] = 0.0f;
#pragma unroll
    for (int i = 0; i < 64; i++) sig4[i] = 0.0f;

    const float inv24 = 1.0f / 24.0f;
    const float inv6  = 1.0f / 6.0f;

    // Software pipeline: preload step 0; inside iteration t, prefetch t+1
    // so LDS latency hides under the 80-FMA block. The final prefetch reads
    // one row past the segment (still inside the smem allocation; unused).
    const float* vp = sm + g * SEG * 8;
    float4 v0 = *(const float4*)vp;
    float4 v1 = *(const float4*)(vp + 4);
    float va = vp[a];
    float vb = vp[bb];

#pragma unroll 1
    for (int t = 0; t < SEG; t++) {
        const float* np = vp + 8;
        float4 n0 = *(const float4*)np;          // prefetch t+1
        float4 n1 = *(const float4*)(np + 4);
        float nva = np[a];
        float nvb = np[bb];
        vp = np;

        // Scalars from OLD s1,s2 (then retire s1,s2 immediately).
        float t6 = fmaf(s1, inv6, va * inv24);   // va/24 + s1/6
        float uu = fmaf(s1, 0.5f, va * inv6);    // va/6  + s1/2
        float m1 = fmaf(vb, t6, s2 * 0.5f);      // vb*t6 + s2/2
        float m2 = fmaf(vb, uu, s2);             // vb*uu + s2
        s2 = fmaf(vb, fmaf(va, 0.5f, s1), s2);   // s2 + va*vb/2 + s1*vb
        s1 += va;

        float K0 = fmaf(v0.x, m1, s3[0]);  s3[0] = fmaf(v0.x, m2, s3[0]);
        float K1 = fmaf(v0.y, m1, s3[1]);  s3[1] = fmaf(v0.y, m2, s3[1]);
        float K2 = fmaf(v0.z, m1, s3[2]);  s3[2] = fmaf(v0.z, m2, s3[2]);
        float K3 = fmaf(v0.w, m1, s3[3]);  s3[3] = fmaf(v0.w, m2, s3[3]);
        float K4 = fmaf(v1.x, m1, s3[4]);  s3[4] = fmaf(v1.x, m2, s3[4]);
        float K5 = fmaf(v1.y, m1, s3[5]);  s3[5] = fmaf(v1.y, m2, s3[5]);
        float K6 = fmaf(v1.z, m1, s3[6]);  s3[6] = fmaf(v1.z, m2, s3[6]);
        float K7 = fmaf(v1.w, m1, s3[7]);  s3[7] = fmaf(v1.w, m2, s3[7]);

#define SIG4ROW(c, Kc)                                            \
        sig4[c*8+0] = fmaf(Kc, v0.x, sig4[c*8+0]);                \
        sig4[c*8+1] = fmaf(Kc, v0.y, sig4[c*8+1]);                \
        sig4[c*8+2] = fmaf(Kc, v0.z, sig4[c*8+2]);                \
        sig4[c*8+3] = fmaf(Kc, v0.w, sig4[c*8+3]);                \
        sig4[c*8+4] = fmaf(Kc, v1.x, sig4[c*8+4]);                \
        sig4[c*8+5] = fmaf(Kc, v1.y, sig4[c*8+5]);                \
        sig4[c*8+6] = fmaf(Kc, v1.z, sig4[c*8+6]);                \
        sig4[c*8+7] = fmaf(Kc, v1.w, sig4[c*8+7]);
        SIG4ROW(0, K0) SIG4ROW(1, K1) SIG4ROW(2, K2) SIG4ROW(3, K3)
        SIG4ROW(4, K4) SIG4ROW(5, K5) SIG4ROW(6, K6) SIG4ROW(7, K7)
#undef SIG4ROW

        v0 = n0; v1 = n1; va = nva; vb = nvb;
    }

    // All scan reads of sm done -> safe to overwrite with T[8][4680].
    __syncthreads();

    float* P = sm + g * SIGCH;
#pragma unroll
    for (int c = 0; c < 8; c++) {
#pragma unroll
        for (int d = 0; d < 8; d++)
            P[584 + u * 64 + c * 8 + d] = sig4[c * 8 + d];
        P[72 + u * 8 + c] = s3[c];
    }
    P[8 + u] = s2;
    if (bb == 0) P[a] = s1;
    __syncthreads();

    // Round 1: 4 parallel in-place combines, 128 threads each.
    {
        int pair = tid >> 7, lane = tid & 127;
        float* A = sm + (2 * pair) * SIGCH;
        const float* B = A + SIGCH;
        chen_inplace(A, B, lane, 128);
    }
    __syncthreads();
    // Round 2: 2 parallel in-place combines, 256 threads each.
    {
        int pair = tid >> 8, lane = tid & 255;
        float* A = sm + (4 * pair) * SIGCH;
        const float* B = A + 2 * SIGCH;
        chen_inplace(A, B, lane, 256);
    }
    __syncthreads();
    // Round 3: final combine straight to global.
    {
        const float* A = sm;
        const float* B = sm + 4 * SIGCH;
        float* y = g_y + (size_t)b * YSTRIDE;
        chen_l4(A, B, y, tid, 512);
        chen_l3(A, B, y, tid, 512);
        if (tid < 64) y[8 + tid] = A[8 + tid] + B[8 + tid] + A[tid >> 3] * B[tid & 7];
        if (tid < 8)  y[tid] = A[tid] + B[tid];
        if (tid < YSTRIDE - SIGCH) y[SIGCH + tid] = 0.0f;
    }
}

// ---------------------------------------------------------------------------
// Kernel 2: split-k GEMM partials. grid = (16 col-groups, KSPLIT).
// CTA: 128 batch-rows x 16 out-cols over KCHUNK of k. 256 threads.
// Tiles padded to 36 floats/row: 16B-aligned for LDS.128, bank-conflict-free.
// ---------------------------------------------------------------------------
__global__ __launch_bounds__(256, 1) void gemm_part_kernel(const float* __restrict__ W)
{
    __shared__ float ys[128][36];
    __shared__ float ws[16][36];

    const int tid = threadIdx.x;
    const int cg = blockIdx.x;
    const int sp = blockIdx.y;
    const int kbase = sp * KCHUNK;

    const int cp = tid & 7;        // col pair: cols 2cp, 2cp+1
    const int rg = tid >> 3;       // rows rg + 32*j

    float acc00 = 0.f, acc01 = 0.f, acc02 = 0.f, acc03 = 0.f;
    float acc10 = 0.f, acc11 = 0.f, acc12 = 0.f, acc13 = 0.f;

    for (int kc = 0; kc < KCHUNK; kc += 32) {
        const int k0 = kbase + kc;
#pragma unroll
        for (int ii = 0; ii < 4; ii++) {
            int lin = tid + 256 * ii;
            int r = lin >> 3, seg = lin & 7;
            float4 val = *(const float4*)&g_y[r * YSTRIDE + k0 + seg * 4];
            *(float4*)&ys[r][seg * 4] = val;
        }
#pragma unroll
        for (int ii = 0; ii < 2; ii++) {
            int lin = tid + 256 * ii;
            int r = lin >> 5, cc = lin & 31;
            int k = k0 + cc;
            ws[r][cc] = (k < SIGCH) ? W[(cg * 16 + r) * SIGCH + k] : 0.0f;
        }
        __syncthreads();
#pragma unroll
        for (int kk = 0; kk < 32; kk += 4) {
            float4 w0 = *(const float4*)&ws[2 * cp][kk];
            float4 w1 = *(const float4*)&ws[2 * cp + 1][kk];
            float4 y0 = *(const float4*)&ys[rg][kk];
            float4 y1 = *(const float4*)&ys[rg + 32][kk];
            float4 y2 = *(const float4*)&ys[rg + 64][kk];
            float4 y3 = *(const float4*)&ys[rg + 96][kk];
            acc00 = fmaf(y0.x, w0.x, acc00); acc00 = fmaf(y0.y, w0.y, acc00);
            acc00 = fmaf(y0.z, w0.z, acc00); acc00 = fmaf(y0.w, w0.w, acc00);
            acc01 = fmaf(y1.x, w0.x, acc01); acc01 = fmaf(y1.y, w0.y, acc01);
            acc01 = fmaf(y1.z, w0.z, acc01); acc01 = fmaf(y1.w, w0.w, acc01);
            acc02 = fmaf(y2.x, w0.x, acc02); acc02 = fmaf(y2.y, w0.y, acc02);
            acc02 = fmaf(y2.z, w0.z, acc02); acc02 = fmaf(y2.w, w0.w, acc02);
            acc03 = fmaf(y3.x, w0.x, acc03); acc03 = fmaf(y3.y, w0.y, acc03);
            acc03 = fmaf(y3.z, w0.z, acc03); acc03 = fmaf(y3.w, w0.w, acc03);
            acc10 = fmaf(y0.x, w1.x, acc10); acc10 = fmaf(y0.y, w1.y, acc10);
            acc10 = fmaf(y0.z, w1.z, acc10); acc10 = fmaf(y0.w, w1.w, acc10);
            acc11 = fmaf(y1.x, w1.x, acc11); acc11 = fmaf(y1.y, w1.y, acc11);
            acc11 = fmaf(y1.z, w1.z, acc11); acc11 = fmaf(y1.w, w1.w, acc11);
            acc12 = fmaf(y2.x, w1.x, acc12); acc12 = fmaf(y2.y, w1.y, acc12);
            acc12 = fmaf(y2.z, w1.z, acc12); acc12 = fmaf(y2.w, w1.w, acc12);
            acc13 = fmaf(y3.x, w1.x, acc13); acc13 = fmaf(y3.y, w1.y, acc13);
            acc13 = fmaf(y3.z, w1.z, acc13); acc13 = fmaf(y3.w, w1.w, acc13);
        }
        __syncthreads();
    }

    const int col0 = cg * 16 + 2 * cp;
    float* p = g_part + (size_t)sp * NB * DOUT;
    p[(rg +  0) * DOUT + col0]     = acc00;
    p[(rg + 32) * DOUT + col0]     = acc01;
    p[(rg + 64) * DOUT + col0]     = acc02;
    p[(rg + 96) * DOUT + col0]     = acc03;
    p[(rg +  0) * DOUT + col0 + 1] = acc10;
    p[(rg + 32) * DOUT + col0 + 1] = acc11;
    p[(rg + 64) * DOUT + col0 + 1] = acc12;
    p[(rg + 96) * DOUT + col0 + 1] = acc13;
}

// ---------------------------------------------------------------------------
__global__ void reduce_bias_kernel(const float* __restrict__ bias, float* __restrict__ out)
{
    int idx = blockIdx.x * 256 + threadIdx.x;
    float v = bias[idx & (DOUT - 1)];
#pragma unroll
    for (int s = 0; s < KSPLIT; s++)
        v += g_part[s * NB * DOUT + idx];
    out[idx] = v;
}

// ---------------------------------------------------------------------------
extern "C" void kernel_launch(void* const* d_in, const int* in_sizes, int n_in,
                              void* d_out, int out_size)
{
    (void)in_sizes; (void)n_in; (void)out_size;
    const float* inp  = (const float*)d_in[0];   // (128,1024,7)
    const float* W    = (const float*)d_in[1];   // (256,4680)
    const float* bias = (const float*)d_in[2];   // (256,)
    float* out = (float*)d_out;                  // (128,256)

    const int smem_bytes = SMEM_FLOATS * sizeof(float);   // 149760
    cudaFuncSetAttribute(sig_scan_kernel,
                         cudaFuncAttributeMaxDynamicSharedMemorySize, smem_bytes);

    sig_scan_kernel<<<NB, 512, smem_bytes>>>(inp);
    dim3 g2(16, KSPLIT);
    gemm_part_kernel<<<g2, 256>>>(W);
    reduce_bias_kernel<<<NB, 256>>>(bias, out);
}